// round 6
// baseline (speedup 1.0000x reference)
#include <cuda_runtime.h>
#include <cuda_bf16.h>
#include <math.h>
#include <stdint.h>

#define S_LEN 2048
#define D_MODEL 2048
#define N_HEADS 16
#define HD 128
#define E3 (3 * D_MODEL)   // 6144

// ---------------- scratch (static device globals; no allocations) -------------
__device__ float g_qkv[(size_t)S_LEN * E3];                      // fp32 qkv
__device__ float g_scores[(size_t)N_HEADS * S_LEN * S_LEN];      // fp32 logits

__device__ __nv_bfloat16 g_xh[(size_t)S_LEN * D_MODEL],  g_xl[(size_t)S_LEN * D_MODEL];
__device__ __nv_bfloat16 g_wqh[(size_t)E3 * D_MODEL],    g_wql[(size_t)E3 * D_MODEL];
__device__ __nv_bfloat16 g_woh[(size_t)D_MODEL * D_MODEL], g_wol[(size_t)D_MODEL * D_MODEL];
__device__ __nv_bfloat16 g_qh[(size_t)S_LEN * D_MODEL],  g_ql[(size_t)S_LEN * D_MODEL];
__device__ __nv_bfloat16 g_kh[(size_t)S_LEN * D_MODEL],  g_kl[(size_t)S_LEN * D_MODEL];
__device__ __nv_bfloat16 g_vth[(size_t)D_MODEL * S_LEN], g_vtl[(size_t)D_MODEL * S_LEN];
__device__ __nv_bfloat16 g_ath[(size_t)S_LEN * D_MODEL], g_atl[(size_t)S_LEN * D_MODEL];
__device__ __nv_bfloat16 g_ph[(size_t)N_HEADS * S_LEN * S_LEN], g_pl[(size_t)N_HEADS * S_LEN * S_LEN];

// =============================================================================
// helpers (base-ISA only: mma.sync / ldmatrix / cp.async — no tcgen05)
// =============================================================================
__device__ __forceinline__ uint32_t smem_u32(const void* p) {
    uint32_t a;
    asm("{ .reg .u64 t; cvta.to.shared.u64 t, %1; cvt.u32.u64 %0, t; }" : "=r"(a) : "l"(p));
    return a;
}
__device__ __forceinline__ void cp16(uint32_t dst, const void* src) {
    asm volatile("cp.async.cg.shared.global [%0], [%1], 16;" :: "r"(dst), "l"(src));
}
#define CP_COMMIT() asm volatile("cp.async.commit_group;" ::: "memory")
#define CP_WAIT(n)  asm volatile("cp.async.wait_group %0;" :: "n"(n) : "memory")

__device__ __forceinline__ void ldm4(uint32_t* r, uint32_t addr) {
    asm volatile("ldmatrix.sync.aligned.m8n8.x4.shared.b16 {%0,%1,%2,%3}, [%4];"
                 : "=r"(r[0]), "=r"(r[1]), "=r"(r[2]), "=r"(r[3]) : "r"(addr));
}
__device__ __forceinline__ void mma16816(float* d, const uint32_t* a, uint32_t b0, uint32_t b1) {
    asm volatile(
        "mma.sync.aligned.m16n8k16.row.col.f32.bf16.bf16.f32 "
        "{%0,%1,%2,%3}, {%4,%5,%6,%7}, {%8,%9}, {%0,%1,%2,%3};"
        : "+f"(d[0]), "+f"(d[1]), "+f"(d[2]), "+f"(d[3])
        : "r"(a[0]), "r"(a[1]), "r"(a[2]), "r"(a[3]), "r"(b0), "r"(b1));
}

__device__ __forceinline__ void split2(float x, __nv_bfloat16& h, __nv_bfloat16& l) {
    h = __float2bfloat16(x);
    l = __float2bfloat16(x - __bfloat162float(h));
}
__device__ __forceinline__ void pack_split(float a, float b, uint32_t& hi, uint32_t& lo) {
    __align__(4) __nv_bfloat16 th[2], tl[2];
    split2(a, th[0], tl[0]); split2(b, th[1], tl[1]);
    hi = *(uint32_t*)th;
    lo = *(uint32_t*)tl;
}

// =============================================================================
// split-bf16 NT GEMM on HMMA: C[m,n] = scale * sum_k A[m,k]*B[n,k]
// A = Ah+Al, B = Bh+Bl. CTA tile 128x128, K-tile 64, cp.async 3-stage pipeline.
// 256 threads, 8 warps as 2(m) x 4(n): warp tile 64x32.
// Separate hi/lo accumulators to shorten HMMA dependency chains.
// Epilogue: fp32 C, or split bf16 (Ch, Cl).
// =============================================================================
#define TILE_B 16384                 // 128 rows * 64 bf16 * 2B
#define STAGE_B (4 * TILE_B)         // Ah, Al, Bh, Bl
#define NSTAGE 3
#define GEMM_SMEM (NSTAGE * STAGE_B) // 192 KB

__global__ void __launch_bounds__(256, 1) gemm_tc_kernel(
    const __nv_bfloat16* __restrict__ Ah, const __nv_bfloat16* __restrict__ Al,
    const __nv_bfloat16* __restrict__ Bh, const __nv_bfloat16* __restrict__ Bl,
    float* __restrict__ C, __nv_bfloat16* __restrict__ Ch, __nv_bfloat16* __restrict__ Cl,
    int K, int lda, int ldb, int ldc,
    long long aZ, long long bZ, long long cZ, float scale)
{
    extern __shared__ __align__(128) char smem[];
    const uint32_t sb = smem_u32(smem);
    const int tid = threadIdx.x;
    const int lane = tid & 31;
    const int wid = tid >> 5;
    const int wm = wid & 1;           // m offset 64*wm
    const int wn = wid >> 1;          // n offset 32*wn (0..3)

    Ah += blockIdx.z * aZ;  Al += blockIdx.z * aZ;
    Bh += blockIdx.z * bZ;  Bl += blockIdx.z * bZ;
    const int m0 = blockIdx.y * 128;
    const int n0 = blockIdx.x * 128;

    float acch[4][4][4];              // Ah*Bh
    float accl[4][4][4];              // Ah*Bl + Al*Bh
#pragma unroll
    for (int a = 0; a < 4; a++)
#pragma unroll
        for (int b = 0; b < 4; b++)
#pragma unroll
            for (int c = 0; c < 4; c++) { acch[a][b][c] = 0.0f; accl[a][b][c] = 0.0f; }

    const int nt = K / 64;

    // ---- stage loader: 256 threads, 4 chunk-iters x 4 tiles ----
    auto load_stage = [&](int t, int buf) {
        const uint32_t base = sb + (uint32_t)buf * STAGE_B;
#pragma unroll
        for (int i = 0; i < 4; i++) {
            const int cid = tid + 256 * i;     // 0..1023
            const int row = cid >> 3;          // 0..127
            const int c   = cid & 7;           // 16B chunk in 128B row
            const uint32_t phys = (uint32_t)(row * 128 + ((c ^ (row & 7)) << 4));
            const size_t ga = (size_t)(m0 + row) * lda + (size_t)t * 64 + c * 8;
            const size_t gb = (size_t)(n0 + row) * ldb + (size_t)t * 64 + c * 8;
            cp16(base + 0 * TILE_B + phys, Ah + ga);
            cp16(base + 1 * TILE_B + phys, Al + ga);
            cp16(base + 2 * TILE_B + phys, Bh + gb);
            cp16(base + 3 * TILE_B + phys, Bl + gb);
        }
        CP_COMMIT();
    };

    load_stage(0, 0);
    if (nt > 1) load_stage(1, 1);

    int buf = 0;
    for (int t = 0; t < nt; t++) {
        // stage t must be resident before compute; keep <=1 group pending
        if (t + 1 < nt) { CP_WAIT(1); } else { CP_WAIT(0); }
        __syncthreads();   // publish stage t data; protect stage (t+2)%3 buffer

        if (t + 2 < nt) {
            int nb = buf + 2; if (nb >= NSTAGE) nb -= NSTAGE;
            load_stage(t + 2, nb);
        }

        const uint32_t tb = sb + (uint32_t)buf * STAGE_B;
#pragma unroll
        for (int k16 = 0; k16 < 4; k16++) {
            const int cb = k16 * 2 + (lane >> 4);     // 16B chunk base for this frag
            uint32_t ah[4][4], al[4][4];
            const int ar = wm * 64 + (lane & 15);
#pragma unroll
            for (int mb = 0; mb < 4; mb++) {
                const int R = ar + mb * 16;
                const uint32_t phys = (uint32_t)(R * 128 + ((cb ^ (R & 7)) << 4));
                ldm4(ah[mb], tb + 0 * TILE_B + phys);
                ldm4(al[mb], tb + 1 * TILE_B + phys);
            }
            uint32_t bh[2][4], bl[2][4];
            const int br = wn * 32 + (lane & 15);
#pragma unroll
            for (int q = 0; q < 2; q++) {
                const int R = br + q * 16;
                const uint32_t phys = (uint32_t)(R * 128 + ((cb ^ (R & 7)) << 4));
                ldm4(bh[q], tb + 2 * TILE_B + phys);
                ldm4(bl[q], tb + 3 * TILE_B + phys);
            }
#pragma unroll
            for (int mb = 0; mb < 4; mb++) {
#pragma unroll
                for (int q = 0; q < 2; q++) {
                    // n-block 2q uses frag regs {0,2}; 2q+1 uses {1,3}
                    mma16816(acch[mb][2 * q],     ah[mb], bh[q][0], bh[q][2]);
                    mma16816(accl[mb][2 * q],     ah[mb], bl[q][0], bl[q][2]);
                    mma16816(accl[mb][2 * q],     al[mb], bh[q][0], bh[q][2]);
                    mma16816(acch[mb][2 * q + 1], ah[mb], bh[q][1], bh[q][3]);
                    mma16816(accl[mb][2 * q + 1], ah[mb], bl[q][1], bl[q][3]);
                    mma16816(accl[mb][2 * q + 1], al[mb], bh[q][1], bh[q][3]);
                }
            }
        }
        if (++buf == NSTAGE) buf = 0;
    }

    // ---- epilogue ----
    const int g  = lane >> 2;
    const int tg = lane & 3;
    if (C) {
        C += blockIdx.z * cZ;
#pragma unroll
        for (int mb = 0; mb < 4; mb++) {
            const int row = m0 + wm * 64 + mb * 16 + g;
#pragma unroll
            for (int nb = 0; nb < 4; nb++) {
                const int col = n0 + wn * 32 + nb * 8 + tg * 2;
                float2 v0, v1;
                v0.x = (acch[mb][nb][0] + accl[mb][nb][0]) * scale;
                v0.y = (acch[mb][nb][1] + accl[mb][nb][1]) * scale;
                v1.x = (acch[mb][nb][2] + accl[mb][nb][2]) * scale;
                v1.y = (acch[mb][nb][3] + accl[mb][nb][3]) * scale;
                *(float2*)(C + (size_t)row * ldc + col)       = v0;
                *(float2*)(C + (size_t)(row + 8) * ldc + col) = v1;
            }
        }
    } else {
        Ch += blockIdx.z * cZ;
        Cl += blockIdx.z * cZ;
#pragma unroll
        for (int mb = 0; mb < 4; mb++) {
            const int row = m0 + wm * 64 + mb * 16 + g;
#pragma unroll
            for (int nb = 0; nb < 4; nb++) {
                const int col = n0 + wn * 32 + nb * 8 + tg * 2;
                uint32_t h0, l0, h1, l1;
                pack_split((acch[mb][nb][0] + accl[mb][nb][0]) * scale,
                           (acch[mb][nb][1] + accl[mb][nb][1]) * scale, h0, l0);
                pack_split((acch[mb][nb][2] + accl[mb][nb][2]) * scale,
                           (acch[mb][nb][3] + accl[mb][nb][3]) * scale, h1, l1);
                *(uint32_t*)(Ch + (size_t)row * ldc + col)       = h0;
                *(uint32_t*)(Cl + (size_t)row * ldc + col)       = l0;
                *(uint32_t*)(Ch + (size_t)(row + 8) * ldc + col) = h1;
                *(uint32_t*)(Cl + (size_t)(row + 8) * ldc + col) = l1;
            }
        }
    }
}

// =============================================================================
// split kernel: fp32 -> (hi, lo) bf16
// =============================================================================
__global__ void __launch_bounds__(256) split_kernel(
    const float* __restrict__ src, __nv_bfloat16* __restrict__ dh,
    __nv_bfloat16* __restrict__ dl, long long n4)
{
    const long long i = (long long)blockIdx.x * 256 + threadIdx.x;
    if (i >= n4) return;
    float4 v = ((const float4*)src)[i];
    __align__(8) __nv_bfloat16 hb[4], lb[4];
    split2(v.x, hb[0], lb[0]); split2(v.y, hb[1], lb[1]);
    split2(v.z, hb[2], lb[2]); split2(v.w, hb[3], lb[3]);
    ((uint2*)dh)[i] = *(uint2*)hb;
    ((uint2*)dl)[i] = *(uint2*)lb;
}

// =============================================================================
// RoPE + split: reads q,k from qkv fp32, writes qh/ql/kh/kl bf16
// =============================================================================
__global__ void __launch_bounds__(1024) rope_split_kernel(
    const float* __restrict__ qkv,
    __nv_bfloat16* __restrict__ qh, __nv_bfloat16* __restrict__ ql,
    __nv_bfloat16* __restrict__ kh, __nv_bfloat16* __restrict__ kl)
{
    __shared__ float s_inv[64];
    const int s = blockIdx.x;
    const int t = threadIdx.x;
    if (t < 64) s_inv[t] = (float)pow(10000.0, -(double)(2 * t) / 128.0);
    __syncthreads();

    const int h = t >> 6;
    const int j = t & 63;
    const float ang = (float)((double)s * (double)s_inv[j]);
    float sn, cs;
    sincosf(ang, &sn, &cs);

    const float* q = qkv + (size_t)s * E3 + h * HD;
    const float* k = q + D_MODEL;
    const size_t ob = (size_t)s * D_MODEL + h * HD;

    const float q1 = q[j], q2 = q[j + 64];
    const float k1 = k[j], k2 = k[j + 64];
    __nv_bfloat16 hh, ll;
    split2(q1 * cs - q2 * sn, hh, ll); qh[ob + j] = hh;      ql[ob + j] = ll;
    split2(q2 * cs + q1 * sn, hh, ll); qh[ob + j + 64] = hh; ql[ob + j + 64] = ll;
    split2(k1 * cs - k2 * sn, hh, ll); kh[ob + j] = hh;      kl[ob + j] = ll;
    split2(k2 * cs + k1 * sn, hh, ll); kh[ob + j + 64] = hh; kl[ob + j + 64] = ll;
}

// =============================================================================
// V transpose + split: vt[c][s] = qkv[s][2D + c]
// =============================================================================
__global__ void __launch_bounds__(256) vtrans_split_kernel(
    const float* __restrict__ qkv,
    __nv_bfloat16* __restrict__ vth, __nv_bfloat16* __restrict__ vtl)
{
    __shared__ float tile[32][33];
    const int c0 = blockIdx.x * 32;
    const int s0 = blockIdx.y * 32;
    const int tx = threadIdx.x & 31;
    const int ty = threadIdx.x >> 5;   // 0..7

#pragma unroll
    for (int r = ty; r < 32; r += 8)
        tile[r][tx] = qkv[(size_t)(s0 + r) * E3 + 2 * D_MODEL + c0 + tx];
    __syncthreads();
#pragma unroll
    for (int r = ty; r < 32; r += 8) {
        const float v = tile[tx][r];
        __nv_bfloat16 hh, ll;
        split2(v, hh, ll);
        const size_t o = (size_t)(c0 + r) * S_LEN + s0 + tx;
        vth[o] = hh;
        vtl[o] = ll;
    }
}

// =============================================================================
// softmax: reads fp32 scores row, writes bf16 split probabilities
// =============================================================================
__global__ void __launch_bounds__(256) softmax_kernel(
    const float* __restrict__ scores,
    __nv_bfloat16* __restrict__ ph, __nv_bfloat16* __restrict__ pl)
{
    const long long row = blockIdx.x;
    const float* p = scores + row * S_LEN;
    const int t = threadIdx.x;
    const int lane = t & 31, warp = t >> 5;

    __shared__ float red[8];

    float4 u0 = ((const float4*)p)[t * 2];
    float4 u1 = ((const float4*)p)[t * 2 + 1];
    float v[8] = {u0.x, u0.y, u0.z, u0.w, u1.x, u1.y, u1.z, u1.w};

    float mx = -INFINITY;
#pragma unroll
    for (int i = 0; i < 8; i++) mx = fmaxf(mx, v[i]);
#pragma unroll
    for (int o = 16; o; o >>= 1) mx = fmaxf(mx, __shfl_xor_sync(0xffffffffu, mx, o));
    if (lane == 0) red[warp] = mx;
    __syncthreads();
    if (t < 32) {
        float x = (t < 8) ? red[t] : -INFINITY;
#pragma unroll
        for (int o = 4; o; o >>= 1) x = fmaxf(x, __shfl_xor_sync(0xffffffffu, x, o));
        if (t == 0) red[0] = x;
    }
    __syncthreads();
    mx = red[0];
    __syncthreads();

    float sum = 0.0f;
#pragma unroll
    for (int i = 0; i < 8; i++) {
        v[i] = __expf(v[i] - mx);
        sum += v[i];
    }
#pragma unroll
    for (int o = 16; o; o >>= 1) sum += __shfl_xor_sync(0xffffffffu, sum, o);
    if (lane == 0) red[warp] = sum;
    __syncthreads();
    if (t < 32) {
        float x = (t < 8) ? red[t] : 0.0f;
#pragma unroll
        for (int o = 4; o; o >>= 1) x += __shfl_xor_sync(0xffffffffu, x, o);
        if (t == 0) red[0] = x;
    }
    __syncthreads();
    const float r = 1.0f / red[0];

    __align__(16) __nv_bfloat16 hb[8], lb[8];
#pragma unroll
    for (int i = 0; i < 8; i++) split2(v[i] * r, hb[i], lb[i]);
    const size_t ob = (size_t)row * S_LEN + (size_t)t * 8;
    *(uint4*)(ph + ob) = *(uint4*)hb;
    *(uint4*)(pl + ob) = *(uint4*)lb;
}

// =============================================================================
// launch
// =============================================================================
extern "C" void kernel_launch(void* const* d_in, const int* in_sizes, int n_in,
                              void* d_out, int out_size)
{
    (void)in_sizes; (void)n_in; (void)out_size;
    const float* x     = (const float*)d_in[0];   // [1, 2048, 2048]
    const float* w_qkv = (const float*)d_in[1];   // [6144, 2048]
    const float* w_out = (const float*)d_in[2];   // [2048, 2048]
    float* out = (float*)d_out;                   // [1, 2048, 2048]

    float *qkv, *scores;
    cudaGetSymbolAddress((void**)&qkv,    g_qkv);
    cudaGetSymbolAddress((void**)&scores, g_scores);
    __nv_bfloat16 *xh, *xl, *wqh, *wql, *woh, *wol, *qh, *ql, *kh, *kl;
    __nv_bfloat16 *vth, *vtl, *ath, *atl, *ph, *pl;
    cudaGetSymbolAddress((void**)&xh,  g_xh);  cudaGetSymbolAddress((void**)&xl,  g_xl);
    cudaGetSymbolAddress((void**)&wqh, g_wqh); cudaGetSymbolAddress((void**)&wql, g_wql);
    cudaGetSymbolAddress((void**)&woh, g_woh); cudaGetSymbolAddress((void**)&wol, g_wol);
    cudaGetSymbolAddress((void**)&qh,  g_qh);  cudaGetSymbolAddress((void**)&ql,  g_ql);
    cudaGetSymbolAddress((void**)&kh,  g_kh);  cudaGetSymbolAddress((void**)&kl,  g_kl);
    cudaGetSymbolAddress((void**)&vth, g_vth); cudaGetSymbolAddress((void**)&vtl, g_vtl);
    cudaGetSymbolAddress((void**)&ath, g_ath); cudaGetSymbolAddress((void**)&atl, g_atl);
    cudaGetSymbolAddress((void**)&ph,  g_ph);  cudaGetSymbolAddress((void**)&pl,  g_pl);

    cudaFuncSetAttribute(gemm_tc_kernel, cudaFuncAttributeMaxDynamicSharedMemorySize, GEMM_SMEM);

    const float scale = 0.08838834764831845f;  // 1/sqrt(128)

    // 0) split inputs
    {
        long long n4;
        n4 = (long long)S_LEN * D_MODEL / 4;
        split_kernel<<<(unsigned)((n4 + 255) / 256), 256>>>(x, xh, xl, n4);
        n4 = (long long)E3 * D_MODEL / 4;
        split_kernel<<<(unsigned)((n4 + 255) / 256), 256>>>(w_qkv, wqh, wql, n4);
        n4 = (long long)D_MODEL * D_MODEL / 4;
        split_kernel<<<(unsigned)((n4 + 255) / 256), 256>>>(w_out, woh, wol, n4);
    }

    // 1) QKV projection: qkv[s,e] = sum_d x[s,d] * w_qkv[e,d]  (fp32 out)
    {
        dim3 grid(E3 / 128, S_LEN / 128, 1);
        gemm_tc_kernel<<<grid, 256, GEMM_SMEM>>>(xh, xl, wqh, wql, qkv, nullptr, nullptr,
                                                 D_MODEL, D_MODEL, D_MODEL, E3,
                                                 0, 0, 0, 1.0f);
    }

    // 2) RoPE + split q,k ; transpose + split v
    rope_split_kernel<<<S_LEN, 1024>>>(qkv, qh, ql, kh, kl);
    {
        dim3 grid(D_MODEL / 32, S_LEN / 32, 1);
        vtrans_split_kernel<<<grid, 256>>>(qkv, vth, vtl);
    }

    // 3) scores[h][q,k] = scale * sum_d Q_h[q,d] * K_h[k,d]  (fp32 out)
    {
        dim3 grid(S_LEN / 128, S_LEN / 128, N_HEADS);
        gemm_tc_kernel<<<grid, 256, GEMM_SMEM>>>(qh, ql, kh, kl, scores, nullptr, nullptr,
                                                 HD, D_MODEL, D_MODEL, S_LEN,
                                                 HD, HD, (long long)S_LEN * S_LEN, scale);
    }

    // 4) softmax -> split bf16 probabilities
    softmax_kernel<<<N_HEADS * S_LEN, 256>>>(scores, ph, pl);

    // 5) att[q, h*128+d] = sum_k P_h[q,k] * Vt_h[d,k]  (split bf16 out, fused)
    {
        dim3 grid(1, S_LEN / 128, N_HEADS);
        gemm_tc_kernel<<<grid, 256, GEMM_SMEM>>>(ph, pl, vth, vtl, nullptr, ath, atl,
                                                 S_LEN, S_LEN, S_LEN, D_MODEL,
                                                 (long long)S_LEN * S_LEN,
                                                 (long long)HD * S_LEN,
                                                 (long long)HD, 1.0f);
    }

    // 6) out[s,o] = sum_d att[s,d] * w_out[o,d]  (fp32 out)
    {
        dim3 grid(D_MODEL / 128, S_LEN / 128, 1);
        gemm_tc_kernel<<<grid, 256, GEMM_SMEM>>>(ath, atl, woh, wol, out, nullptr, nullptr,
                                                 D_MODEL, D_MODEL, D_MODEL, D_MODEL,
                                                 0, 0, 0, 1.0f);
    }
}